// round 7
// baseline (speedup 1.0000x reference)
#include <cuda_runtime.h>
#include <math.h>
#include <stdint.h>

#define N_NODES 10000
#define HID 128
#define EDIM 416
#define N_EDGES 160000
#define K1 (2*HID+EDIM)              // 672
#define X_OUT_ELEMS (N_NODES*HID)    // 1,280,000

// -------- scratch (device globals; no allocations allowed) --------
__device__ __align__(128) float g_xh[N_NODES*HID];
__device__ __align__(128) float g_agg[N_NODES*HID];
__device__ __align__(128) float g_cnt[N_NODES];
__device__ __align__(128) float g_n1[N_NODES*HID];
// pre-transposed weights: WT[n][k]
__device__ __align__(128) float g_WeT1[128*672];
__device__ __align__(128) float g_We2T[128*128];
__device__ __align__(128) float g_WoT[512*128];       // rows 416..511 zero

__device__ __forceinline__ float silu_f(float x){ return x / (1.0f + __expf(-x)); }
__device__ __forceinline__ uint32_t smem_u32(const void* p){
    uint32_t a;
    asm("{ .reg .u64 t; cvta.to.shared.u64 t, %1; cvt.u32.u64 %0, t; }" : "=r"(a) : "l"(p));
    return a;
}
// tf32 MMA on raw fp32 bit patterns (HW reads high 19 bits)
__device__ __forceinline__ void mma8(float* c, const uint32_t* a, uint32_t b0, uint32_t b1){
    asm volatile("mma.sync.aligned.m16n8k8.row.col.f32.tf32.tf32.f32 "
        "{%0,%1,%2,%3}, {%4,%5,%6,%7}, {%8,%9}, {%0,%1,%2,%3};"
        : "+f"(c[0]), "+f"(c[1]), "+f"(c[2]), "+f"(c[3])
        : "r"(a[0]), "r"(a[1]), "r"(a[2]), "r"(a[3]), "r"(b0), "r"(b1));
}

#define CP_ASYNC16(dst, src) \
    asm volatile("cp.async.cg.shared.global [%0], [%1], 16;" :: "r"(dst), "l"(src) : "memory")
#define CP_COMMIT() asm volatile("cp.async.commit_group;" ::: "memory")
#define CP_WAIT(n)  asm volatile("cp.async.wait_group %0;" :: "n"(n) : "memory")

// swizzled word index inside a 128-row x 32-word tile (rows 128B, 16B chunks XOR'd by row)
__device__ __forceinline__ int swzi(int r, int k){
    return r*32 + ((((k >> 2) ^ r) & 7) << 2) + (k & 3);
}
// dynamic smem layout (uint32 words):
//   sM      : 4 K-blocks x 4096 = 16384 words (64KB) — m1/m_ij tile, swizzled per K-block
//   stageA  : 3 x 4096 (48KB)
//   stageB  : 3 x 4096 (48KB)
#define SM_WORDS   16384
#define STG_WORDS  4096
#define NSTAGE     3
#define OFF_A(st)  (SM_WORDS + (st)*STG_WORDS)
#define OFF_B(st)  (SM_WORDS + NSTAGE*STG_WORDS + (st)*STG_WORDS)
#define SMEM_BYTES ((SM_WORDS + 2*NSTAGE*STG_WORDS)*4)   // 160KB

// ================= setup: zero agg/cnt + transpose weights =================
__global__ void setup_kernel(const float* __restrict__ We1, const float* __restrict__ We2,
                             const float* __restrict__ Wo){
    int i = blockIdx.x*blockDim.x + threadIdx.x;
    if (i < N_NODES*HID) g_agg[i] = 0.0f;
    if (i < N_NODES)     g_cnt[i] = 0.0f;
    if (i < 128*672){ int n = i/672, k = i%672; g_WeT1[i] = We1[k*128 + n]; }
    if (i < 128*128){ int n = i/128, k = i%128; g_We2T[i] = We2[k*128 + n]; }
    if (i < 512*128){ int n = i/128, k = i%128; g_WoT[i] = (n < EDIM) ? Wo[k*EDIM + n] : 0.0f; }
}

// -------- layernorm --------
__global__ void ln_kernel(const float* __restrict__ x,
                          const float* __restrict__ g,
                          const float* __restrict__ b){
    int row = blockIdx.x*8 + threadIdx.y;
    if (row >= N_NODES) return;
    int lane = threadIdx.x;
    float4 v = ((const float4*)(x + row*HID))[lane];
    float s = v.x + v.y + v.z + v.w;
    #pragma unroll
    for (int o = 16; o > 0; o >>= 1) s += __shfl_xor_sync(0xffffffffu, s, o);
    float mu = s * (1.0f/HID);
    float dx = v.x-mu, dy = v.y-mu, dz = v.z-mu, dw = v.w-mu;
    float q = dx*dx + dy*dy + dz*dz + dw*dw;
    #pragma unroll
    for (int o = 16; o > 0; o >>= 1) q += __shfl_xor_sync(0xffffffffu, q, o);
    float rstd = rsqrtf(q*(1.0f/HID) + 1e-5f);
    float4 gg = ((const float4*)g)[lane];
    float4 bb = ((const float4*)b)[lane];
    float4 o4;
    o4.x = dx*rstd*gg.x + bb.x;
    o4.y = dy*rstd*gg.y + bb.y;
    o4.z = dz*rstd*gg.z + bb.z;
    o4.w = dw*rstd*gg.w + bb.w;
    ((float4*)(g_xh + row*HID))[lane] = o4;
}

// ============ FUSED edge kernel: 512 threads, 16 warps (4x4 grid), warp tile 32x32 ============
// One MMA pass over a staged/resident tile pair.
#define MMA_TILE32(tA, tB) do { \
    _Pragma("unroll") \
    for (int k0 = 0; k0 < 32; k0 += 8){ \
        uint32_t a[2][4]; \
        _Pragma("unroll") \
        for (int mt = 0; mt < 2; mt++){ \
            int R0 = wm + mt*16 + lr; \
            a[mt][0] = (tA)[swzi(R0,     k0 + lc)]; \
            a[mt][1] = (tA)[swzi(R0 + 8, k0 + lc)]; \
            a[mt][2] = (tA)[swzi(R0,     k0 + 4 + lc)]; \
            a[mt][3] = (tA)[swzi(R0 + 8, k0 + 4 + lc)]; \
        } \
        _Pragma("unroll") \
        for (int nt = 0; nt < 4; nt++){ \
            int n = wn + nt*8 + lr; \
            uint32_t b0 = (tB)[swzi(n, k0 + lc)]; \
            uint32_t b1 = (tB)[swzi(n, k0 + 4 + lc)]; \
            _Pragma("unroll") \
            for (int mt = 0; mt < 2; mt++) mma8(acc[mt][nt], a[mt], b0, b1); \
        } \
    } \
} while(0)

#define ACC_ZERO() do { \
    _Pragma("unroll") \
    for (int i = 0; i < 2; i++) \
        _Pragma("unroll") \
        for (int j = 0; j < 4; j++){ acc[i][j][0]=0; acc[i][j][1]=0; acc[i][j][2]=0; acc[i][j][3]=0; } \
} while(0)

__global__ void __launch_bounds__(512, 1)
edge_fused(const float* __restrict__ be1, const float* __restrict__ be2,
           const float* __restrict__ Wa,  const float* __restrict__ ba,
           const float* __restrict__ bo,  const float* __restrict__ weight,
           const int* __restrict__ ei,    float* __restrict__ out){
    extern __shared__ uint32_t dynsm[];
    __shared__ float sB1[128], sB2[128], sWa[128], s_att[128], sBo[512];
    __shared__ int s_ii[128], s_jj[128];
    const int tid = threadIdx.x;
    const int e0  = blockIdx.x*128;
    if (tid < 128){
        s_ii[tid] = ei[e0 + tid];
        s_jj[tid] = ei[N_EDGES + e0 + tid];
        sB1[tid] = be1[tid];
        sB2[tid] = be2[tid];
        sWa[tid] = Wa[tid];
        s_att[tid] = 0.0f;
    }
    sBo[tid] = (tid < EDIM) ? bo[tid] : 0.0f;
    __syncthreads();

    const uint32_t sbase = smem_u32(dynsm);
    const int lane = tid & 31, lr = lane >> 2, lc = lane & 3;
    const int wid = tid >> 5;
    const int wm = (wid & 3)*32, wn = (wid >> 2)*32;
    const int lr9 = tid >> 3, lc8 = tid & 7;   // loader coords: rows tid>>3 (+64), chunk col tid&7
    float acc[2][4][4];

    // ================== PHASE 1: m1 = silu([xh_i|xh_j|w] @ We1 + be1) -> sM ==================
    ACC_ZERO();
    #define ISSUE_P1(st, kt) do { \
        uint32_t ab = sbase + OFF_A(st)*4u; \
        uint32_t bb = sbase + OFF_B(st)*4u; \
        _Pragma("unroll") \
        for (int i = 0; i < 2; i++){ \
            int r = lr9 + i*64, c = lc8; \
            int kg = (kt) + c*4; \
            const void* srcA; \
            if (kg < HID)        srcA = g_xh + s_ii[r]*HID + kg; \
            else if (kg < 2*HID) srcA = g_xh + s_jj[r]*HID + (kg - HID); \
            else                 srcA = weight + (size_t)(e0 + r)*EDIM + (kg - 2*HID); \
            uint32_t off = (uint32_t)(r*32 + (((c ^ r) & 7) << 2))*4u; \
            CP_ASYNC16(ab + off, srcA); \
            CP_ASYNC16(bb + off, (const void*)(g_WeT1 + (size_t)r*K1 + kg)); \
        } \
        CP_COMMIT(); \
    } while(0)

    {
        const int T = K1/32;   // 21
        ISSUE_P1(0, 0);
        ISSUE_P1(1, 32);
        int st = 0;
        for (int t = 0; t < T; t++){
            if (t + 1 < T) CP_WAIT(1); else CP_WAIT(0);
            __syncthreads();
            if (t + 2 < T){
                int s2 = st + 2; if (s2 >= NSTAGE) s2 -= NSTAGE;
                ISSUE_P1(s2, (t+2)*32);
            }
            MMA_TILE32(dynsm + OFF_A(st), dynsm + OFF_B(st));
            if (++st == NSTAGE) st = 0;
        }
    }
    #undef ISSUE_P1
    // epilogue -> sM (swizzled K-block layout)
    __syncthreads();   // staging reads done everywhere before... (not strictly needed, cheap)
    #pragma unroll
    for (int mt = 0; mt < 2; mt++){
        int r1 = wm + mt*16 + lr, r2 = r1 + 8;
        #pragma unroll
        for (int nt = 0; nt < 4; nt++){
            int c = wn + nt*8 + lc*2;
            int kb = c >> 5, kk = c & 31;
            float2 v1, v2;
            v1.x = silu_f(acc[mt][nt][0] + sB1[c]);
            v1.y = silu_f(acc[mt][nt][1] + sB1[c+1]);
            v2.x = silu_f(acc[mt][nt][2] + sB1[c]);
            v2.y = silu_f(acc[mt][nt][3] + sB1[c+1]);
            *(float2*)&dynsm[kb*4096 + swzi(r1, kk)] = v1;
            *(float2*)&dynsm[kb*4096 + swzi(r2, kk)] = v2;
        }
    }
    __syncthreads();

    // ================== PHASE 2: m2 = silu(m1 @ We2 + be2); att; m_ij -> sM; agg ==================
    ACC_ZERO();
    #define ISSUE_B(st, src_row_base, kt) do { \
        uint32_t bb = sbase + OFF_B(st)*4u; \
        _Pragma("unroll") \
        for (int i = 0; i < 2; i++){ \
            int r = lr9 + i*64, c = lc8; \
            uint32_t off = (uint32_t)(r*32 + (((c ^ r) & 7) << 2))*4u; \
            CP_ASYNC16(bb + off, (const void*)((src_row_base) + (size_t)r*HID + (kt) + c*4)); \
        } \
        CP_COMMIT(); \
    } while(0)

    {
        ISSUE_B(0, g_We2T, 0);
        ISSUE_B(1, g_We2T, 32);
        int st = 0;
        for (int t = 0; t < 4; t++){
            if (t + 1 < 4) CP_WAIT(1); else CP_WAIT(0);
            __syncthreads();
            if (t + 2 < 4){
                int s2 = st + 2; if (s2 >= NSTAGE) s2 -= NSTAGE;
                ISSUE_B(s2, g_We2T, (t+2)*32);
            }
            MMA_TILE32(dynsm + t*4096, dynsm + OFF_B(st));
            if (++st == NSTAGE) st = 0;
        }
    }
    // silu + partial attention dots
    #pragma unroll
    for (int mt = 0; mt < 2; mt++){
        float p0 = 0.0f, p1 = 0.0f;
        #pragma unroll
        for (int nt = 0; nt < 4; nt++){
            int c = wn + nt*8 + lc*2;
            float wa0 = sWa[c], wa1 = sWa[c+1];
            float v0 = silu_f(acc[mt][nt][0] + sB2[c]);
            float v1 = silu_f(acc[mt][nt][1] + sB2[c+1]);
            float v2 = silu_f(acc[mt][nt][2] + sB2[c]);
            float v3 = silu_f(acc[mt][nt][3] + sB2[c+1]);
            acc[mt][nt][0]=v0; acc[mt][nt][1]=v1; acc[mt][nt][2]=v2; acc[mt][nt][3]=v3;
            p0 += v0*wa0 + v1*wa1;
            p1 += v2*wa0 + v3*wa1;
        }
        atomicAdd(&s_att[wm + mt*16 + lr], p0);
        atomicAdd(&s_att[wm + mt*16 + lr + 8], p1);
    }
    __syncthreads();   // s_att complete AND all phase-2 sM reads done (WAR)
    {
        const float ba0 = ba[0];
        #pragma unroll
        for (int mt = 0; mt < 2; mt++){
            int r1 = wm + mt*16 + lr, r2 = r1 + 8;
            float att1 = silu_f(s_att[r1] + ba0);
            float att2 = silu_f(s_att[r2] + ba0);
            int n1 = s_ii[r1], n2 = s_ii[r2];
            #pragma unroll
            for (int nt = 0; nt < 4; nt++){
                int c = wn + nt*8 + lc*2;
                int kb = c >> 5, kk = c & 31;
                float2 v1, v2;
                v1.x = acc[mt][nt][0]*att1; v1.y = acc[mt][nt][1]*att1;
                v2.x = acc[mt][nt][2]*att2; v2.y = acc[mt][nt][3]*att2;
                *(float2*)&dynsm[kb*4096 + swzi(r1, kk)] = v1;
                *(float2*)&dynsm[kb*4096 + swzi(r2, kk)] = v2;
                asm volatile("red.global.add.v2.f32 [%0], {%1,%2};"
                             :: "l"(g_agg + (size_t)n1*HID + c), "f"(v1.x), "f"(v1.y) : "memory");
                asm volatile("red.global.add.v2.f32 [%0], {%1,%2};"
                             :: "l"(g_agg + (size_t)n2*HID + c), "f"(v2.x), "f"(v2.y) : "memory");
            }
        }
        if (tid < 128) atomicAdd(&g_cnt[s_ii[tid]], 1.0f);
    }
    __syncthreads();   // m_ij visible in sM before phase 3

    // ================== PHASE 3: edgeh = weight + silu(m_ij @ Wo + bo), 4 N-blocks ==================
    {
        ISSUE_B(0, g_WoT, 0);                       // idx 0: nb=0,t=0 -> rows 0..127, k 0..31
        ISSUE_B(1, g_WoT + (size_t)0*HID, 32);      // idx 1: nb=0,t=1
        int st = 0;
        for (int idx = 0; idx < 16; idx++){
            int nb = idx >> 2, tt = idx & 3;
            if (tt == 0) ACC_ZERO();
            if (idx + 1 < 16) CP_WAIT(1); else CP_WAIT(0);
            __syncthreads();
            if (idx + 2 < 16){
                int s2 = st + 2; if (s2 >= NSTAGE) s2 -= NSTAGE;
                int i2 = idx + 2, nb2 = i2 >> 2, tt2 = i2 & 3;
                ISSUE_B(s2, g_WoT + (size_t)nb2*128*HID, tt2*32);
            }
            MMA_TILE32(dynsm + tt*4096, dynsm + OFF_B(st));
            if (++st == NSTAGE) st = 0;
            if (tt == 3){
                // epilogue for this N-block
                #pragma unroll
                for (int mt = 0; mt < 2; mt++){
                    int r1 = e0 + wm + mt*16 + lr;
                    #pragma unroll
                    for (int nt = 0; nt < 4; nt++){
                        int c = wn + nt*8 + lc*2;
                        int g = nb*128 + c;
                        if (g < EDIM){
                            float2 w1 = *(const float2*)(weight + (size_t)r1*EDIM + g);
                            float2 w2 = *(const float2*)(weight + (size_t)(r1+8)*EDIM + g);
                            float2 v1, v2;
                            v1.x = w1.x + silu_f(acc[mt][nt][0] + sBo[g]);
                            v1.y = w1.y + silu_f(acc[mt][nt][1] + sBo[g+1]);
                            v2.x = w2.x + silu_f(acc[mt][nt][2] + sBo[g]);
                            v2.y = w2.y + silu_f(acc[mt][nt][3] + sBo[g+1]);
                            *(float2*)(out + X_OUT_ELEMS + (size_t)r1*EDIM + g) = v1;
                            *(float2*)(out + X_OUT_ELEMS + (size_t)(r1+8)*EDIM + g) = v2;
                        }
                    }
                }
            }
        }
    }
    #undef ISSUE_B
}

// ================= scalar node kernels =================
__global__ void __launch_bounds__(256) node_mlp1_kernel(const float* __restrict__ Wn1,
                                                        const float* __restrict__ bn1){
    __shared__ float sA[64*33];
    __shared__ float sB[32*128];
    __shared__ float s_inv[64];
    const int tid = threadIdx.x;
    const int r0  = blockIdx.x*64;
    if (tid < 64){
        int node = min(r0 + tid, N_NODES - 1);
        float c = g_cnt[node];
        s_inv[tid] = 1.0f / ((c == 0.0f) ? 1.0f : c);
    }
    __syncthreads();
    const int m0 = (tid >> 5)*8;
    const int n0 = (tid & 31)*4;
    float acc[8][4];
    #pragma unroll
    for (int i = 0; i < 8; i++){ acc[i][0]=0; acc[i][1]=0; acc[i][2]=0; acc[i][3]=0; }

    for (int kt = 0; kt < 2*HID; kt += 32){
        #pragma unroll
        for (int i = 0; i < 8; i++){
            int idx = tid + i*256;
            int r = idx >> 5, k = idx & 31;
            int kg = kt + k;
            int node = min(r0 + r, N_NODES - 1);
            float v = (kg < HID) ? g_xh[node*HID + kg]
                                 : g_agg[node*HID + (kg - HID)] * s_inv[r];
            sA[r*33 + k] = v;
        }
        #pragma unroll
        for (int i = 0; i < 16; i++){
            int idx = tid + i*256;
            int k = idx >> 7, n = idx & 127;
            sB[k*128 + n] = Wn1[(kt + k)*128 + n];
        }
        __syncthreads();
        #pragma unroll
        for (int kk = 0; kk < 32; kk++){
            float4 bv = *(const float4*)&sB[kk*128 + n0];
            #pragma unroll
            for (int i = 0; i < 8; i++){
                float a = sA[(m0+i)*33 + kk];
                acc[i][0] += a*bv.x; acc[i][1] += a*bv.y;
                acc[i][2] += a*bv.z; acc[i][3] += a*bv.w;
            }
        }
        __syncthreads();
    }
    float4 bias = *(const float4*)&bn1[n0];
    #pragma unroll
    for (int i = 0; i < 8; i++){
        int row = r0 + m0 + i;
        if (row < N_NODES){
            float4 o;
            o.x = silu_f(acc[i][0] + bias.x);
            o.y = silu_f(acc[i][1] + bias.y);
            o.z = silu_f(acc[i][2] + bias.z);
            o.w = silu_f(acc[i][3] + bias.w);
            *(float4*)&g_n1[row*HID + n0] = o;
        }
    }
}

__global__ void __launch_bounds__(256) node_mlp2_kernel(const float* __restrict__ Wn2,
                                                        const float* __restrict__ bn2,
                                                        float* __restrict__ out){
    __shared__ float sA[64*33];
    __shared__ float sB[32*128];
    const int tid = threadIdx.x;
    const int r0  = blockIdx.x*64;
    const int m0 = (tid >> 5)*8;
    const int n0 = (tid & 31)*4;
    float acc[8][4];
    #pragma unroll
    for (int i = 0; i < 8; i++){ acc[i][0]=0; acc[i][1]=0; acc[i][2]=0; acc[i][3]=0; }

    for (int kt = 0; kt < HID; kt += 32){
        #pragma unroll
        for (int i = 0; i < 8; i++){
            int idx = tid + i*256;
            int r = idx >> 5, k = idx & 31;
            int node = min(r0 + r, N_NODES - 1);
            sA[r*33 + k] = g_n1[node*HID + kt + k];
        }
        #pragma unroll
        for (int i = 0; i < 16; i++){
            int idx = tid + i*256;
            int k = idx >> 7, n = idx & 127;
            sB[k*128 + n] = Wn2[(kt + k)*128 + n];
        }
        __syncthreads();
        #pragma unroll
        for (int kk = 0; kk < 32; kk++){
            float4 bv = *(const float4*)&sB[kk*128 + n0];
            #pragma unroll
            for (int i = 0; i < 8; i++){
                float a = sA[(m0+i)*33 + kk];
                acc[i][0] += a*bv.x; acc[i][1] += a*bv.y;
                acc[i][2] += a*bv.z; acc[i][3] += a*bv.w;
            }
        }
        __syncthreads();
    }
    float4 bias = *(const float4*)&bn2[n0];
    #pragma unroll
    for (int i = 0; i < 8; i++){
        int row = r0 + m0 + i;
        if (row < N_NODES){
            float4 xh4 = *(const float4*)&g_xh[row*HID + n0];
            float4 o;
            o.x = xh4.x + silu_f(acc[i][0] + bias.x);
            o.y = xh4.y + silu_f(acc[i][1] + bias.y);
            o.z = xh4.z + silu_f(acc[i][2] + bias.z);
            o.w = xh4.w + silu_f(acc[i][3] + bias.w);
            *(float4*)&out[row*HID + n0] = o;
        }
    }
}

extern "C" void kernel_launch(void* const* d_in, const int* in_sizes, int n_in,
                              void* d_out, int out_size){
    const float* x    = (const float*)d_in[0];
    const float* wgt  = (const float*)d_in[1];
    const float* ln_g = (const float*)d_in[2];
    const float* ln_b = (const float*)d_in[3];
    const float* We1  = (const float*)d_in[4];
    const float* be1  = (const float*)d_in[5];
    const float* We2  = (const float*)d_in[6];
    const float* be2  = (const float*)d_in[7];
    const float* Wa   = (const float*)d_in[8];
    const float* ba   = (const float*)d_in[9];
    const float* Wn1  = (const float*)d_in[10];
    const float* bn1  = (const float*)d_in[11];
    const float* Wn2  = (const float*)d_in[12];
    const float* bn2  = (const float*)d_in[13];
    const float* Wo   = (const float*)d_in[14];
    const float* bo   = (const float*)d_in[15];
    const int*   ei   = (const int*)d_in[16];
    float* out = (float*)d_out;

    cudaFuncSetAttribute(edge_fused, cudaFuncAttributeMaxDynamicSharedMemorySize, SMEM_BYTES);

    setup_kernel<<<(N_NODES*HID + 255)/256, 256>>>(We1, We2, Wo);
    ln_kernel<<<(N_NODES + 7)/8, dim3(32, 8)>>>(x, ln_g, ln_b);
    edge_fused<<<N_EDGES/128, 512, SMEM_BYTES>>>(be1, be2, Wa, ba, bo, wgt, ei, out);
    node_mlp1_kernel<<<(N_NODES + 63)/64, 256>>>(Wn1, bn1);
    node_mlp2_kernel<<<(N_NODES + 63)/64, 256>>>(Wn2, bn2, out);
}

// round 8
// speedup vs baseline: 1.0713x; 1.0713x over previous
#include <cuda_runtime.h>
#include <math.h>
#include <stdint.h>

#define N_NODES 10000
#define NODES_PAD 10112              // 79 * 128
#define HID 128
#define EDIM 416
#define N_EDGES 160000
#define K1 (2*HID+EDIM)              // 672
#define X_OUT_ELEMS (N_NODES*HID)

// -------- scratch (device globals; no allocations allowed) --------
__device__ __align__(128) float g_xh[NODES_PAD*HID];    // padding stays zero
__device__ __align__(128) float g_m[N_EDGES*HID];       // m1, then m_ij
__device__ __align__(128) float g_agg[NODES_PAD*HID];   // mean-scaled agg
__device__ __align__(128) float g_n1[NODES_PAD*HID];
// pre-transposed weights: WT[n][k]
__device__ __align__(128) float g_WeT1[128*672];
__device__ __align__(128) float g_We2T[128*128];
__device__ __align__(128) float g_WoT[512*128];         // rows 416..511 zero
__device__ __align__(128) float g_WnT1[128*256];
__device__ __align__(128) float g_Wn2T[128*128];
// CSR
__device__ int g_deg[10016];
__device__ int g_off[10017];
__device__ int g_cur[10016];
__device__ int g_elist[N_EDGES];

__device__ __forceinline__ float silu_f(float x){ return x / (1.0f + __expf(-x)); }
__device__ __forceinline__ uint32_t smem_u32(const void* p){
    uint32_t a;
    asm("{ .reg .u64 t; cvta.to.shared.u64 t, %1; cvt.u32.u64 %0, t; }" : "=r"(a) : "l"(p));
    return a;
}
// tf32 MMA on raw fp32 bit patterns (HW reads high 19 bits)
__device__ __forceinline__ void mma8(float* c, const uint32_t* a, uint32_t b0, uint32_t b1){
    asm volatile("mma.sync.aligned.m16n8k8.row.col.f32.tf32.tf32.f32 "
        "{%0,%1,%2,%3}, {%4,%5,%6,%7}, {%8,%9}, {%0,%1,%2,%3};"
        : "+f"(c[0]), "+f"(c[1]), "+f"(c[2]), "+f"(c[3])
        : "r"(a[0]), "r"(a[1]), "r"(a[2]), "r"(a[3]), "r"(b0), "r"(b1));
}
#define CP_ASYNC16(dst, src) \
    asm volatile("cp.async.cg.shared.global [%0], [%1], 16;" :: "r"(dst), "l"(src) : "memory")
#define CP_COMMIT() asm volatile("cp.async.commit_group;" ::: "memory")
#define CP_WAIT(n)  asm volatile("cp.async.wait_group %0;" :: "n"(n) : "memory")

__device__ __forceinline__ int swzi(int r, int k){
    return r*32 + ((((k >> 2) ^ r) & 7) << 2) + (k & 3);
}
#define STG_WORDS  4096
#define NSTAGE     3
#define OFF_A(st)  ((st)*STG_WORDS)
#define OFF_B(st)  (NSTAGE*STG_WORDS + (st)*STG_WORDS)
#define SMEM_STD   (2*NSTAGE*STG_WORDS*4)          // 96KB (A+B 3-stage)
#define SM_WORDS   16384
#define SMEM_EO    ((SM_WORDS + 2*STG_WORDS)*4)    // 96KB (resident A + B 2-stage)

// ================= setup =================
__global__ void setup_kernel(const float* __restrict__ We1, const float* __restrict__ We2,
                             const float* __restrict__ Wo,  const float* __restrict__ Wn1,
                             const float* __restrict__ Wn2){
    int i = blockIdx.x*blockDim.x + threadIdx.x;
    if (i < 10016) g_deg[i] = 0;
    if (i < 128*672){ int n = i/672, k = i%672; g_WeT1[i] = We1[k*128 + n]; }
    if (i < 128*128){ int n = i/128, k = i%128; g_We2T[i] = We2[k*128 + n]; }
    if (i < 512*128){ int n = i/128, k = i%128; g_WoT[i] = (n < EDIM) ? Wo[k*EDIM + n] : 0.0f; }
    if (i < 128*256){ int n = i/256, k = i%256; g_WnT1[i] = Wn1[k*128 + n]; }
    if (i < 128*128){ int n = i/128, k = i%128; g_Wn2T[i] = Wn2[k*128 + n]; }
}

// -------- layernorm --------
__global__ void ln_kernel(const float* __restrict__ x,
                          const float* __restrict__ g,
                          const float* __restrict__ b){
    int row = blockIdx.x*8 + threadIdx.y;
    if (row >= N_NODES) return;
    int lane = threadIdx.x;
    float4 v = ((const float4*)(x + row*HID))[lane];
    float s = v.x + v.y + v.z + v.w;
    #pragma unroll
    for (int o = 16; o > 0; o >>= 1) s += __shfl_xor_sync(0xffffffffu, s, o);
    float mu = s * (1.0f/HID);
    float dx = v.x-mu, dy = v.y-mu, dz = v.z-mu, dw = v.w-mu;
    float q = dx*dx + dy*dy + dz*dz + dw*dw;
    #pragma unroll
    for (int o = 16; o > 0; o >>= 1) q += __shfl_xor_sync(0xffffffffu, q, o);
    float rstd = rsqrtf(q*(1.0f/HID) + 1e-5f);
    float4 gg = ((const float4*)g)[lane];
    float4 bb = ((const float4*)b)[lane];
    float4 o4;
    o4.x = dx*rstd*gg.x + bb.x;
    o4.y = dy*rstd*gg.y + bb.y;
    o4.z = dz*rstd*gg.z + bb.z;
    o4.w = dw*rstd*gg.w + bb.w;
    ((float4*)(g_xh + row*HID))[lane] = o4;
}

// ================= CSR build =================
__global__ void hist_kernel(const int* __restrict__ ei){
    int e = blockIdx.x*blockDim.x + threadIdx.x;
    if (e < N_EDGES) atomicAdd(&g_deg[ei[e]], 1);
}
__global__ void scan_kernel(){
    __shared__ int s[1024];
    int t = threadIdx.x;
    int base = t*10;
    int sum = 0;
    #pragma unroll
    for (int j = 0; j < 10; j++){
        int i = base + j;
        if (i < 10016) sum += g_deg[i];
    }
    s[t] = sum;
    __syncthreads();
    for (int off = 1; off < 1024; off <<= 1){
        int v = (t >= off) ? s[t-off] : 0;
        __syncthreads();
        s[t] += v;
        __syncthreads();
    }
    int run = s[t] - sum;
    #pragma unroll
    for (int j = 0; j < 10; j++){
        int i = base + j;
        if (i < 10016){
            g_off[i] = run;
            g_cur[i] = run;
            run += g_deg[i];
        }
    }
    if (t == 1023) g_off[10016] = run;
}
__global__ void scatter_kernel(const int* __restrict__ ei){
    int e = blockIdx.x*blockDim.x + threadIdx.x;
    if (e < N_EDGES){
        int n = ei[e];
        int p = atomicAdd(&g_cur[n], 1);
        g_elist[p] = e;
    }
}
// warp-per-node gather aggregation (mean): g_agg[n] = sum(m_ij[e]) / max(deg,1)
__global__ void __launch_bounds__(1024) agg_kernel(){
    int wid = threadIdx.x >> 5, lane = threadIdx.x & 31;
    int n = blockIdx.x*32 + wid;
    if (n >= N_NODES) return;
    int o0 = g_off[n], o1 = g_off[n+1];
    float4 acc = make_float4(0.f, 0.f, 0.f, 0.f);
    int i = o0;
    for (; i + 1 < o1; i += 2){
        int e0 = g_elist[i], e1 = g_elist[i+1];
        float4 v0 = *(const float4*)(g_m + (size_t)e0*HID + lane*4);
        float4 v1 = *(const float4*)(g_m + (size_t)e1*HID + lane*4);
        acc.x += v0.x + v1.x; acc.y += v0.y + v1.y;
        acc.z += v0.z + v1.z; acc.w += v0.w + v1.w;
    }
    if (i < o1){
        int e0 = g_elist[i];
        float4 v0 = *(const float4*)(g_m + (size_t)e0*HID + lane*4);
        acc.x += v0.x; acc.y += v0.y; acc.z += v0.z; acc.w += v0.w;
    }
    int deg = o1 - o0;
    float s = (deg > 0) ? 1.0f/(float)deg : 1.0f;
    float4 o;
    o.x = acc.x*s; o.y = acc.y*s; o.z = acc.z*s; o.w = acc.w*s;
    *(float4*)(g_agg + (size_t)n*HID + lane*4) = o;
}

// ============ pipelined MMA kernels: 128x128 tile, 8 warps (2x4), warp tile 64x32 ============
#define MMA_TILE(tA, tB) do { \
    _Pragma("unroll") \
    for (int k0 = 0; k0 < 32; k0 += 8){ \
        uint32_t a[4][4]; \
        _Pragma("unroll") \
        for (int mt = 0; mt < 4; mt++){ \
            int R0 = wm + mt*16 + lr; \
            a[mt][0] = (tA)[swzi(R0,     k0 + lc)]; \
            a[mt][1] = (tA)[swzi(R0 + 8, k0 + lc)]; \
            a[mt][2] = (tA)[swzi(R0,     k0 + 4 + lc)]; \
            a[mt][3] = (tA)[swzi(R0 + 8, k0 + 4 + lc)]; \
        } \
        _Pragma("unroll") \
        for (int nt = 0; nt < 4; nt++){ \
            int n = wn + nt*8 + lr; \
            uint32_t b0 = (tB)[swzi(n, k0 + lc)]; \
            uint32_t b1 = (tB)[swzi(n, k0 + 4 + lc)]; \
            _Pragma("unroll") \
            for (int mt = 0; mt < 4; mt++) mma8(acc[mt][nt], a[mt], b0, b1); \
        } \
    } \
} while(0)
#define ACC_ZERO4() do { \
    _Pragma("unroll") \
    for (int i = 0; i < 4; i++) \
        _Pragma("unroll") \
        for (int j = 0; j < 4; j++){ acc[i][j][0]=0; acc[i][j][1]=0; acc[i][j][2]=0; acc[i][j][3]=0; } \
} while(0)

// -------- edge MLP layer 1 --------
__global__ void __launch_bounds__(256, 2) edge_mlp1_mma(const float* __restrict__ be1,
                                                        const float* __restrict__ weight,
                                                        const int* __restrict__ ei){
    extern __shared__ uint32_t dynsm[];
    __shared__ float sBias[128];
    __shared__ int s_ii[128], s_jj[128];
    const int tid = threadIdx.x;
    const int e0  = blockIdx.x*128;
    if (tid < 128){
        s_ii[tid] = ei[e0 + tid];
        s_jj[tid] = ei[N_EDGES + e0 + tid];
        sBias[tid] = be1[tid];
    }
    __syncthreads();
    const uint32_t sbase = smem_u32(dynsm);
    const int lane = tid & 31, lr = lane >> 2, lc = lane & 3;
    const int wid = tid >> 5;
    const int wm = (wid & 1)*64, wn = (wid >> 1)*32;
    float acc[4][4][4];
    ACC_ZERO4();
    const int lr8 = tid >> 3, lc8 = tid & 7;

    #define ISSUE1(st, kt) do { \
        uint32_t ab = sbase + OFF_A(st)*4u; \
        uint32_t bb = sbase + OFF_B(st)*4u; \
        _Pragma("unroll") \
        for (int i = 0; i < 4; i++){ \
            int r = lr8 + i*32, c = lc8; \
            int kg = (kt) + c*4; \
            const void* srcA; \
            if (kg < HID)        srcA = g_xh + s_ii[r]*HID + kg; \
            else if (kg < 2*HID) srcA = g_xh + s_jj[r]*HID + (kg - HID); \
            else                 srcA = weight + (size_t)(e0 + r)*EDIM + (kg - 2*HID); \
            uint32_t off = (uint32_t)(r*32 + (((c ^ r) & 7) << 2))*4u; \
            CP_ASYNC16(ab + off, srcA); \
            CP_ASYNC16(bb + off, (const void*)(g_WeT1 + (size_t)r*K1 + kg)); \
        } \
        CP_COMMIT(); \
    } while(0)

    const int T = K1/32;   // 21
    ISSUE1(0, 0);
    ISSUE1(1, 32);
    int st = 0;
    for (int t = 0; t < T; t++){
        if (t + 1 < T) CP_WAIT(1); else CP_WAIT(0);
        __syncthreads();
        if (t + 2 < T){
            int s2 = st + 2; if (s2 >= NSTAGE) s2 -= NSTAGE;
            ISSUE1(s2, (t+2)*32);
        }
        MMA_TILE(dynsm + OFF_A(st), dynsm + OFF_B(st));
        if (++st == NSTAGE) st = 0;
    }
    #undef ISSUE1
    #pragma unroll
    for (int mt = 0; mt < 4; mt++){
        int r1 = wm + mt*16 + lr;
        #pragma unroll
        for (int nt = 0; nt < 4; nt++){
            int c = wn + nt*8 + lc*2;
            float2 v1, v2;
            v1.x = silu_f(acc[mt][nt][0] + sBias[c]);
            v1.y = silu_f(acc[mt][nt][1] + sBias[c+1]);
            v2.x = silu_f(acc[mt][nt][2] + sBias[c]);
            v2.y = silu_f(acc[mt][nt][3] + sBias[c+1]);
            *(float2*)(g_m + (size_t)(e0 + r1)*HID + c) = v1;
            *(float2*)(g_m + (size_t)(e0 + r1 + 8)*HID + c) = v2;
        }
    }
}

// -------- edge MLP layer 2 + attention + gated message (NO atomics) --------
__global__ void __launch_bounds__(256, 2) edge_mlp2_mma(const float* __restrict__ be2,
                                                        const float* __restrict__ Wa,
                                                        const float* __restrict__ ba){
    extern __shared__ uint32_t dynsm[];
    __shared__ float sBias[128], sWa[128], s_att[128];
    const int tid = threadIdx.x;
    const int e0  = blockIdx.x*128;
    if (tid < 128){
        sBias[tid] = be2[tid];
        sWa[tid] = Wa[tid];
        s_att[tid] = 0.0f;
    }
    __syncthreads();
    const uint32_t sbase = smem_u32(dynsm);
    const int lane = tid & 31, lr = lane >> 2, lc = lane & 3;
    const int wid = tid >> 5;
    const int wm = (wid & 1)*64, wn = (wid >> 1)*32;
    float acc[4][4][4];
    ACC_ZERO4();
    const int lr8 = tid >> 3, lc8 = tid & 7;

    #define ISSUE2(st, kt) do { \
        uint32_t ab = sbase + OFF_A(st)*4u; \
        uint32_t bb = sbase + OFF_B(st)*4u; \
        _Pragma("unroll") \
        for (int i = 0; i < 4; i++){ \
            int r = lr8 + i*32, c = lc8; \
            int kg = (kt) + c*4; \
            uint32_t off = (uint32_t)(r*32 + (((c ^ r) & 7) << 2))*4u; \
            CP_ASYNC16(ab + off, (const void*)(g_m + (size_t)(e0 + r)*HID + kg)); \
            CP_ASYNC16(bb + off, (const void*)(g_We2T + (size_t)r*HID + kg)); \
        } \
        CP_COMMIT(); \
    } while(0)

    ISSUE2(0, 0);
    ISSUE2(1, 32);
    int st = 0;
    for (int t = 0; t < 4; t++){
        if (t + 1 < 4) CP_WAIT(1); else CP_WAIT(0);
        __syncthreads();
        if (t + 2 < 4){
            int s2 = st + 2; if (s2 >= NSTAGE) s2 -= NSTAGE;
            ISSUE2(s2, (t+2)*32);
        }
        MMA_TILE(dynsm + OFF_A(st), dynsm + OFF_B(st));
        if (++st == NSTAGE) st = 0;
    }
    #undef ISSUE2
    #pragma unroll
    for (int mt = 0; mt < 4; mt++){
        float p0 = 0.0f, p1 = 0.0f;
        #pragma unroll
        for (int nt = 0; nt < 4; nt++){
            int c = wn + nt*8 + lc*2;
            float wa0 = sWa[c], wa1 = sWa[c+1];
            float v0 = silu_f(acc[mt][nt][0] + sBias[c]);
            float v1 = silu_f(acc[mt][nt][1] + sBias[c+1]);
            float v2 = silu_f(acc[mt][nt][2] + sBias[c]);
            float v3 = silu_f(acc[mt][nt][3] + sBias[c+1]);
            acc[mt][nt][0]=v0; acc[mt][nt][1]=v1; acc[mt][nt][2]=v2; acc[mt][nt][3]=v3;
            p0 += v0*wa0 + v1*wa1;
            p1 += v2*wa0 + v3*wa1;
        }
        atomicAdd(&s_att[wm + mt*16 + lr], p0);
        atomicAdd(&s_att[wm + mt*16 + lr + 8], p1);
    }
    __syncthreads();
    const float ba0 = ba[0];
    #pragma unroll
    for (int mt = 0; mt < 4; mt++){
        int r1 = wm + mt*16 + lr, r2 = r1 + 8;
        float att1 = silu_f(s_att[r1] + ba0);
        float att2 = silu_f(s_att[r2] + ba0);
        #pragma unroll
        for (int nt = 0; nt < 4; nt++){
            int c = wn + nt*8 + lc*2;
            float2 v1, v2;
            v1.x = acc[mt][nt][0]*att1; v1.y = acc[mt][nt][1]*att1;
            v2.x = acc[mt][nt][2]*att2; v2.y = acc[mt][nt][3]*att2;
            *(float2*)(g_m + (size_t)(e0 + r1)*HID + c) = v1;
            *(float2*)(g_m + (size_t)(e0 + r2)*HID + c) = v2;
        }
    }
}

// -------- edge out: resident A (m_ij tile) + loop over 4 N-blocks --------
__global__ void __launch_bounds__(256, 2) edge_out_mma(const float* __restrict__ bo,
                                                       const float* __restrict__ weight,
                                                       float* __restrict__ out){
    extern __shared__ uint32_t dynsm[];   // [0, SM_WORDS): A (4 k-blocks); then B 2-stage
    __shared__ float sBias[512];
    const int tid = threadIdx.x;
    const int e0  = blockIdx.x*128;
    sBias[tid] = (tid < EDIM) ? bo[tid] : 0.0f;
    sBias[tid+256] = (tid+256 < EDIM) ? bo[tid+256] : 0.0f;
    __syncthreads();
    const uint32_t sbase = smem_u32(dynsm);
    const int lane = tid & 31, lr = lane >> 2, lc = lane & 3;
    const int wid = tid >> 5;
    const int wm = (wid & 1)*64, wn = (wid >> 1)*32;
    float acc[4][4][4];
    const int lr8 = tid >> 3, lc8 = tid & 7;

    // load A (m_ij 128x128) into sM: 4 k-blocks, swizzled
    #pragma unroll
    for (int kb = 0; kb < 4; kb++){
        #pragma unroll
        for (int i = 0; i < 4; i++){
            int r = lr8 + i*32, c = lc8;
            uint32_t off = (uint32_t)(kb*4096 + r*32 + (((c ^ r) & 7) << 2))*4u;
            CP_ASYNC16(sbase + off, (const void*)(g_m + (size_t)(e0 + r)*HID + kb*32 + c*4));
        }
    }
    CP_COMMIT();

    #define ISSUE_EO(st, idx) do { \
        int nb_ = (idx) >> 2, tt_ = (idx) & 3; \
        uint32_t bb = sbase + (SM_WORDS + (st)*STG_WORDS)*4u; \
        _Pragma("unroll") \
        for (int i = 0; i < 4; i++){ \
            int r = lr8 + i*32, c = lc8; \
            uint32_t off = (uint32_t)(r*32 + (((c ^ r) & 7) << 2))*4u; \
            CP_ASYNC16(bb + off, (const void*)(g_WoT + (size_t)(nb_*128 + r)*HID + tt_*32 + c*4)); \
        } \
        CP_COMMIT(); \
    } while(0)

    ISSUE_EO(0, 0);
    for (int idx = 0; idx < 16; idx++){
        int nb = idx >> 2, tt = idx & 3, st = idx & 1;
        if (tt == 0) ACC_ZERO4();
        CP_WAIT(0);
        __syncthreads();
        if (idx + 1 < 16) ISSUE_EO((idx+1)&1, idx+1);
        MMA_TILE(dynsm + tt*4096, dynsm + SM_WORDS + st*STG_WORDS);
        if (tt == 3){
            #pragma unroll
            for (int mt = 0; mt < 4; mt++){
                int r1 = e0 + wm + mt*16 + lr;
                #pragma unroll
                for (int nt = 0; nt < 4; nt++){
                    int c = wn + nt*8 + lc*2;
                    int g = nb*128 + c;
                    if (g < EDIM){
                        float2 w1 = *(const float2*)(weight + (size_t)r1*EDIM + g);
                        float2 w2 = *(const float2*)(weight + (size_t)(r1+8)*EDIM + g);
                        float2 v1, v2;
                        v1.x = w1.x + silu_f(acc[mt][nt][0] + sBias[g]);
                        v1.y = w1.y + silu_f(acc[mt][nt][1] + sBias[g+1]);
                        v2.x = w2.x + silu_f(acc[mt][nt][2] + sBias[g]);
                        v2.y = w2.y + silu_f(acc[mt][nt][3] + sBias[g+1]);
                        *(float2*)(out + X_OUT_ELEMS + (size_t)r1*EDIM + g) = v1;
                        *(float2*)(out + X_OUT_ELEMS + (size_t)(r1+8)*EDIM + g) = v2;
                    }
                }
            }
        }
    }
    #undef ISSUE_EO
}

// -------- node MLP 1 (MMA): n1 = silu([xh | agg] @ Wn1 + bn1) --------
__global__ void __launch_bounds__(256, 2) node_mlp1_mma(const float* __restrict__ bn1){
    extern __shared__ uint32_t dynsm[];
    __shared__ float sBias[128];
    const int tid = threadIdx.x;
    const int r0  = blockIdx.x*128;
    if (tid < 128) sBias[tid] = bn1[tid];
    __syncthreads();
    const uint32_t sbase = smem_u32(dynsm);
    const int lane = tid & 31, lr = lane >> 2, lc = lane & 3;
    const int wid = tid >> 5;
    const int wm = (wid & 1)*64, wn = (wid >> 1)*32;
    float acc[4][4][4];
    ACC_ZERO4();
    const int lr8 = tid >> 3, lc8 = tid & 7;

    #define ISSUE_N1(st, kt) do { \
        uint32_t ab = sbase + OFF_A(st)*4u; \
        uint32_t bb = sbase + OFF_B(st)*4u; \
        _Pragma("unroll") \
        for (int i = 0; i < 4; i++){ \
            int r = lr8 + i*32, c = lc8; \
            int kg = (kt) + c*4; \
            const void* srcA = (kg < HID) ? (const void*)(g_xh + (size_t)(r0 + r)*HID + kg) \
                                          : (const void*)(g_agg + (size_t)(r0 + r)*HID + (kg - HID)); \
            uint32_t off = (uint32_t)(r*32 + (((c ^ r) & 7) << 2))*4u; \
            CP_ASYNC16(ab + off, srcA); \
            CP_ASYNC16(bb + off, (const void*)(g_WnT1 + (size_t)r*256 + kg)); \
        } \
        CP_COMMIT(); \
    } while(0)

    ISSUE_N1(0, 0);
    ISSUE_N1(1, 32);
    int st = 0;
    for (int t = 0; t < 8; t++){
        if (t + 1 < 8) CP_WAIT(1); else CP_WAIT(0);
        __syncthreads();
        if (t + 2 < 8){
            int s2 = st + 2; if (s2 >= NSTAGE) s2 -= NSTAGE;
            ISSUE_N1(s2, (t+2)*32);
        }
        MMA_TILE(dynsm + OFF_A(st), dynsm + OFF_B(st));
        if (++st == NSTAGE) st = 0;
    }
    #undef ISSUE_N1
    #pragma unroll
    for (int mt = 0; mt < 4; mt++){
        int r1 = r0 + wm + mt*16 + lr;
        #pragma unroll
        for (int nt = 0; nt < 4; nt++){
            int c = wn + nt*8 + lc*2;
            float2 v1, v2;
            v1.x = silu_f(acc[mt][nt][0] + sBias[c]);
            v1.y = silu_f(acc[mt][nt][1] + sBias[c+1]);
            v2.x = silu_f(acc[mt][nt][2] + sBias[c]);
            v2.y = silu_f(acc[mt][nt][3] + sBias[c+1]);
            *(float2*)(g_n1 + (size_t)r1*HID + c) = v1;
            *(float2*)(g_n1 + (size_t)(r1+8)*HID + c) = v2;
        }
    }
}

// -------- node MLP 2 (MMA) + residual --------
__global__ void __launch_bounds__(256, 2) node_mlp2_mma(const float* __restrict__ bn2,
                                                        float* __restrict__ out){
    extern __shared__ uint32_t dynsm[];
    __shared__ float sBias[128];
    const int tid = threadIdx.x;
    const int r0  = blockIdx.x*128;
    if (tid < 128) sBias[tid] = bn2[tid];
    __syncthreads();
    const uint32_t sbase = smem_u32(dynsm);
    const int lane = tid & 31, lr = lane >> 2, lc = lane & 3;
    const int wid = tid >> 5;
    const int wm = (wid & 1)*64, wn = (wid >> 1)*32;
    float acc[4][4][4];
    ACC_ZERO4();
    const int lr8 = tid >> 3, lc8 = tid & 7;

    #define ISSUE_N2(st, kt) do { \
        uint32_t ab = sbase + OFF_A(st)*4u; \
        uint32_t bb = sbase + OFF_B(st)*4u; \
        _Pragma("unroll") \
        for (int i = 0; i < 4; i++){ \
            int r = lr8 + i*32, c = lc8; \
            int kg = (kt) + c*4; \
            uint32_t off = (uint32_t)(r*32 + (((c ^ r) & 7) << 2))*4u; \
            CP_ASYNC16(ab + off, (const void*)(g_n1 + (size_t)(r0 + r)*HID + kg)); \
            CP_ASYNC16(bb + off, (const void*)(g_Wn2T + (size_t)r*HID + kg)); \
        } \
        CP_COMMIT(); \
    } while(0)

    ISSUE_N2(0, 0);
    ISSUE_N2(1, 32);
    int st = 0;
    for (int t = 0; t < 4; t++){
        if (t + 1 < 4) CP_WAIT(1); else CP_WAIT(0);
        __syncthreads();
        if (t + 2 < 4){
            int s2 = st + 2; if (s2 >= NSTAGE) s2 -= NSTAGE;
            ISSUE_N2(s2, (t+2)*32);
        }
        MMA_TILE(dynsm + OFF_A(st), dynsm + OFF_B(st));
        if (++st == NSTAGE) st = 0;
    }
    #undef ISSUE_N2
    #pragma unroll
    for (int mt = 0; mt < 4; mt++){
        int r1 = r0 + wm + mt*16 + lr;
        #pragma unroll
        for (int nt = 0; nt < 4; nt++){
            int c = wn + nt*8 + lc*2;
            if (r1 < N_NODES){
                float2 xh1 = *(const float2*)(g_xh + (size_t)r1*HID + c);
                float2 v1;
                v1.x = xh1.x + silu_f(acc[mt][nt][0] + sBias[c]);
                v1.y = xh1.y + silu_f(acc[mt][nt][1] + sBias[c+1]);
                *(float2*)(out + (size_t)r1*HID + c) = v1;
            }
            if (r1 + 8 < N_NODES){
                float2 xh2 = *(const float2*)(g_xh + (size_t)(r1+8)*HID + c);
                float2 v2;
                v2.x = xh2.x + silu_f(acc[mt][nt][2] + sBias[c]);
                v2.y = xh2.y + silu_f(acc[mt][nt][3] + sBias[c+1]);
                *(float2*)(out + (size_t)(r1+8)*HID + c) = v2;
            }
        }
    }
}

extern "C" void kernel_launch(void* const* d_in, const int* in_sizes, int n_in,
                              void* d_out, int out_size){
    const float* x    = (const float*)d_in[0];
    const float* wgt  = (const float*)d_in[1];
    const float* ln_g = (const float*)d_in[2];
    const float* ln_b = (const float*)d_in[3];
    const float* We1  = (const float*)d_in[4];
    const float* be1  = (const float*)d_in[5];
    const float* We2  = (const float*)d_in[6];
    const float* be2  = (const float*)d_in[7];
    const float* Wa   = (const float*)d_in[8];
    const float* ba   = (const float*)d_in[9];
    const float* Wn1  = (const float*)d_in[10];
    const float* bn1  = (const float*)d_in[11];
    const float* Wn2  = (const float*)d_in[12];
    const float* bn2  = (const float*)d_in[13];
    const float* Wo   = (const float*)d_in[14];
    const float* bo   = (const float*)d_in[15];
    const int*   ei   = (const int*)d_in[16];
    float* out = (float*)d_out;

    cudaFuncSetAttribute(edge_mlp1_mma, cudaFuncAttributeMaxDynamicSharedMemorySize, SMEM_STD);
    cudaFuncSetAttribute(edge_mlp2_mma, cudaFuncAttributeMaxDynamicSharedMemorySize, SMEM_STD);
    cudaFuncSetAttribute(edge_out_mma,  cudaFuncAttributeMaxDynamicSharedMemorySize, SMEM_EO);
    cudaFuncSetAttribute(node_mlp1_mma, cudaFuncAttributeMaxDynamicSharedMemorySize, SMEM_STD);
    cudaFuncSetAttribute(node_mlp2_mma, cudaFuncAttributeMaxDynamicSharedMemorySize, SMEM_STD);

    setup_kernel<<<(1280000 + 255)/256, 256>>>(We1, We2, Wo, Wn1, Wn2);
    ln_kernel<<<(N_NODES + 7)/8, dim3(32, 8)>>>(x, ln_g, ln_b);
    hist_kernel<<<(N_EDGES + 255)/256, 256>>>(ei);
    scan_kernel<<<1, 1024>>>();
    scatter_kernel<<<(N_EDGES + 255)/256, 256>>>(ei);
    edge_mlp1_mma<<<N_EDGES/128, 256, SMEM_STD>>>(be1, wgt, ei);
    edge_mlp2_mma<<<N_EDGES/128, 256, SMEM_STD>>>(be2, Wa, ba);
    agg_kernel<<<(N_NODES + 31)/32, 1024>>>();
    node_mlp1_mma<<<NODES_PAD/128, 256, SMEM_STD>>>(bn1);
    node_mlp2_mma<<<NODES_PAD/128, 256, SMEM_STD>>>(bn2, out);
    edge_out_mma<<<N_EDGES/128, 256, SMEM_EO>>>(bo, wgt, out);
}

// round 9
// speedup vs baseline: 1.1358x; 1.0602x over previous
#include <cuda_runtime.h>
#include <math.h>
#include <stdint.h>

#define N_NODES 10000
#define NODES_PAD 10112              // 79 * 128
#define HID 128
#define EDIM 416
#define N_EDGES 160000
#define X_OUT_ELEMS (N_NODES*HID)

// -------- scratch (device globals; no allocations allowed) --------
__device__ __align__(128) float g_xh[NODES_PAD*HID];    // padding stays zero
__device__ __align__(128) float g_m[N_EDGES*HID];       // m1, then m_ij
__device__ __align__(128) float g_agg[NODES_PAD*HID];
__device__ __align__(128) float g_n1[NODES_PAD*HID];
__device__ __align__(128) float g_P[NODES_PAD*256];     // [xh@Wi | xh@Wj]
// pre-transposed weights
__device__ __align__(128) float g_WijT[256*128];        // rows 0..127: Wi^T, 128..255: Wj^T
__device__ __align__(128) float g_WwT[128*EDIM];        // We1 weight-part ^T : [n][k0..415]
__device__ __align__(128) float g_We2T[128*128];
__device__ __align__(128) float g_WoT[512*128];         // rows 416..511 zero
__device__ __align__(128) float g_WnT1[128*256];
__device__ __align__(128) float g_Wn2T[128*128];
// CSR
__device__ int g_deg[10016];
__device__ int g_off[10017];
__device__ int g_cur[10016];
__device__ int g_elist[N_EDGES];

__device__ __forceinline__ float silu_f(float x){ return x / (1.0f + __expf(-x)); }
__device__ __forceinline__ uint32_t smem_u32(const void* p){
    uint32_t a;
    asm("{ .reg .u64 t; cvta.to.shared.u64 t, %1; cvt.u32.u64 %0, t; }" : "=r"(a) : "l"(p));
    return a;
}
__device__ __forceinline__ void mma8(float* c, const uint32_t* a, uint32_t b0, uint32_t b1){
    asm volatile("mma.sync.aligned.m16n8k8.row.col.f32.tf32.tf32.f32 "
        "{%0,%1,%2,%3}, {%4,%5,%6,%7}, {%8,%9}, {%0,%1,%2,%3};"
        : "+f"(c[0]), "+f"(c[1]), "+f"(c[2]), "+f"(c[3])
        : "r"(a[0]), "r"(a[1]), "r"(a[2]), "r"(a[3]), "r"(b0), "r"(b1));
}
#define CP_ASYNC16(dst, src) \
    asm volatile("cp.async.cg.shared.global [%0], [%1], 16;" :: "r"(dst), "l"(src) : "memory")
#define CP_COMMIT() asm volatile("cp.async.commit_group;" ::: "memory")
#define CP_WAIT(n)  asm volatile("cp.async.wait_group %0;" :: "n"(n) : "memory")

__device__ __forceinline__ int swzi(int r, int k){
    return r*32 + ((((k >> 2) ^ r) & 7) << 2) + (k & 3);
}
#define STG_WORDS  4096
#define NSTAGE     3
#define OFF_A(st)  ((st)*STG_WORDS)
#define OFF_B(st)  (NSTAGE*STG_WORDS + (st)*STG_WORDS)
#define SMEM_STD   (2*NSTAGE*STG_WORDS*4)          // 96KB
#define SM_WORDS   16384
#define SMEM_EO    ((SM_WORDS + 2*STG_WORDS)*4)    // 96KB

// ================= setup =================
__global__ void setup_kernel(const float* __restrict__ We1, const float* __restrict__ We2,
                             const float* __restrict__ Wo,  const float* __restrict__ Wn1,
                             const float* __restrict__ Wn2){
    int i = blockIdx.x*blockDim.x + threadIdx.x;   // grid covers 65536
    if (i < 10016) g_deg[i] = 0;
    if (i < 256*128){ int n = i/128, k = i%128;
        g_WijT[i] = (n < 128) ? We1[k*128 + n] : We1[(128 + k)*128 + (n - 128)]; }
    if (i < 128*EDIM){ int n = i/EDIM, k = i%EDIM; g_WwT[i] = We1[(256 + k)*128 + n]; }
    if (i < 128*128){ int n = i/128, k = i%128; g_We2T[i] = We2[k*128 + n]; }
    if (i < 512*128){ int n = i/128, k = i%128; g_WoT[i] = (n < EDIM) ? Wo[k*EDIM + n] : 0.0f; }
    if (i < 128*256){ int n = i/256, k = i%256; g_WnT1[i] = Wn1[k*128 + n]; }
    if (i < 128*128){ int n = i/128, k = i%128; g_Wn2T[i] = Wn2[k*128 + n]; }
}

// -------- layernorm --------
__global__ void ln_kernel(const float* __restrict__ x,
                          const float* __restrict__ g,
                          const float* __restrict__ b){
    int row = blockIdx.x*8 + threadIdx.y;
    if (row >= N_NODES) return;
    int lane = threadIdx.x;
    float4 v = ((const float4*)(x + row*HID))[lane];
    float s = v.x + v.y + v.z + v.w;
    #pragma unroll
    for (int o = 16; o > 0; o >>= 1) s += __shfl_xor_sync(0xffffffffu, s, o);
    float mu = s * (1.0f/HID);
    float dx = v.x-mu, dy = v.y-mu, dz = v.z-mu, dw = v.w-mu;
    float q = dx*dx + dy*dy + dz*dz + dw*dw;
    #pragma unroll
    for (int o = 16; o > 0; o >>= 1) q += __shfl_xor_sync(0xffffffffu, q, o);
    float rstd = rsqrtf(q*(1.0f/HID) + 1e-5f);
    float4 gg = ((const float4*)g)[lane];
    float4 bb = ((const float4*)b)[lane];
    float4 o4;
    o4.x = dx*rstd*gg.x + bb.x;
    o4.y = dy*rstd*gg.y + bb.y;
    o4.z = dz*rstd*gg.z + bb.z;
    o4.w = dw*rstd*gg.w + bb.w;
    ((float4*)(g_xh + row*HID))[lane] = o4;
}

// ================= CSR build =================
__global__ void hist_kernel(const int* __restrict__ ei){
    int e = blockIdx.x*blockDim.x + threadIdx.x;
    if (e < N_EDGES) atomicAdd(&g_deg[ei[e]], 1);
}
__global__ void __launch_bounds__(1024) scan_kernel(){
    __shared__ int warp_sums[32];
    int t = threadIdx.x;
    int base = t*10;
    int loc[10];
    int sum = 0;
    #pragma unroll
    for (int j = 0; j < 10; j++){
        int i = base + j;
        int v = (i < 10016) ? g_deg[i] : 0;
        loc[j] = sum; sum += v;
    }
    int lane = t & 31, w = t >> 5;
    int incl = sum;
    #pragma unroll
    for (int o = 1; o < 32; o <<= 1){
        int v = __shfl_up_sync(0xffffffffu, incl, o);
        if (lane >= o) incl += v;
    }
    if (lane == 31) warp_sums[w] = incl;
    __syncthreads();
    if (w == 0){
        int ws = warp_sums[lane];
        #pragma unroll
        for (int o = 1; o < 32; o <<= 1){
            int v = __shfl_up_sync(0xffffffffu, ws, o);
            if (lane >= o) ws += v;
        }
        warp_sums[lane] = ws;
    }
    __syncthreads();
    int offset = incl - sum + ((w > 0) ? warp_sums[w-1] : 0);
    #pragma unroll
    for (int j = 0; j < 10; j++){
        int i = base + j;
        if (i < 10016){ int o = offset + loc[j]; g_off[i] = o; g_cur[i] = o; }
    }
    if (t == 1023) g_off[10016] = offset + sum;
}
__global__ void scatter_kernel(const int* __restrict__ ei){
    int e = blockIdx.x*blockDim.x + threadIdx.x;
    if (e < N_EDGES){
        int n = ei[e];
        int p = atomicAdd(&g_cur[n], 1);
        g_elist[p] = e;
    }
}
// warp-per-node gather mean aggregation
__global__ void __launch_bounds__(1024) agg_kernel(){
    int wid = threadIdx.x >> 5, lane = threadIdx.x & 31;
    int n = blockIdx.x*32 + wid;
    if (n >= N_NODES) return;
    int o0 = g_off[n], o1 = g_off[n+1];
    float4 acc = make_float4(0.f, 0.f, 0.f, 0.f);
    int i = o0;
    for (; i + 1 < o1; i += 2){
        int e0 = g_elist[i], e1 = g_elist[i+1];
        float4 v0 = *(const float4*)(g_m + (size_t)e0*HID + lane*4);
        float4 v1 = *(const float4*)(g_m + (size_t)e1*HID + lane*4);
        acc.x += v0.x + v1.x; acc.y += v0.y + v1.y;
        acc.z += v0.z + v1.z; acc.w += v0.w + v1.w;
    }
    if (i < o1){
        int e0 = g_elist[i];
        float4 v0 = *(const float4*)(g_m + (size_t)e0*HID + lane*4);
        acc.x += v0.x; acc.y += v0.y; acc.z += v0.z; acc.w += v0.w;
    }
    int deg = o1 - o0;
    float s = (deg > 0) ? 1.0f/(float)deg : 1.0f;
    float4 o;
    o.x = acc.x*s; o.y = acc.y*s; o.z = acc.z*s; o.w = acc.w*s;
    *(float4*)(g_agg + (size_t)n*HID + lane*4) = o;
}

// ============ MMA core: 128x128 tile, 8 warps (2x4), warp tile 64x32 ============
#define MMA_TILE(tA, tB) do { \
    _Pragma("unroll") \
    for (int k0 = 0; k0 < 32; k0 += 8){ \
        uint32_t a[4][4]; \
        _Pragma("unroll") \
        for (int mt = 0; mt < 4; mt++){ \
            int R0 = wm + mt*16 + lr; \
            a[mt][0] = (tA)[swzi(R0,     k0 + lc)]; \
            a[mt][1] = (tA)[swzi(R0 + 8, k0 + lc)]; \
            a[mt][2] = (tA)[swzi(R0,     k0 + 4 + lc)]; \
            a[mt][3] = (tA)[swzi(R0 + 8, k0 + 4 + lc)]; \
        } \
        _Pragma("unroll") \
        for (int nt = 0; nt < 4; nt++){ \
            int n = wn + nt*8 + lr; \
            uint32_t b0 = (tB)[swzi(n, k0 + lc)]; \
            uint32_t b1 = (tB)[swzi(n, k0 + 4 + lc)]; \
            _Pragma("unroll") \
            for (int mt = 0; mt < 4; mt++) mma8(acc[mt][nt], a[mt], b0, b1); \
        } \
    } \
} while(0)
#define ACC_ZERO4() do { \
    _Pragma("unroll") \
    for (int i = 0; i < 4; i++) \
        _Pragma("unroll") \
        for (int j = 0; j < 4; j++){ acc[i][j][0]=0; acc[i][j][1]=0; acc[i][j][2]=0; acc[i][j][3]=0; } \
} while(0)

// -------- pre: P = xh @ [Wi | Wj]  (grid: 79 x 2) --------
__global__ void __launch_bounds__(256, 2) pre_P_mma(){
    extern __shared__ uint32_t dynsm[];
    const int tid = threadIdx.x;
    const int r0  = blockIdx.x*128;
    const int nb  = blockIdx.y;           // 0: Wi, 1: Wj
    const uint32_t sbase = smem_u32(dynsm);
    const int lane = tid & 31, lr = lane >> 2, lc = lane & 3;
    const int wid = tid >> 5;
    const int wm = (wid & 1)*64, wn = (wid >> 1)*32;
    float acc[4][4][4];
    ACC_ZERO4();
    const int lr8 = tid >> 3, lc8 = tid & 7;

    #define ISSUE_P(st, kt) do { \
        uint32_t ab = sbase + OFF_A(st)*4u; \
        uint32_t bb = sbase + OFF_B(st)*4u; \
        _Pragma("unroll") \
        for (int i = 0; i < 4; i++){ \
            int r = lr8 + i*32, c = lc8; \
            int kg = (kt) + c*4; \
            uint32_t off = (uint32_t)(r*32 + (((c ^ r) & 7) << 2))*4u; \
            CP_ASYNC16(ab + off, (const void*)(g_xh + (size_t)(r0 + r)*HID + kg)); \
            CP_ASYNC16(bb + off, (const void*)(g_WijT + (size_t)(nb*128 + r)*HID + kg)); \
        } \
        CP_COMMIT(); \
    } while(0)

    ISSUE_P(0, 0);
    ISSUE_P(1, 32);
    int st = 0;
    for (int t = 0; t < 4; t++){
        if (t + 1 < 4) CP_WAIT(1); else CP_WAIT(0);
        __syncthreads();
        if (t + 2 < 4){
            int s2 = st + 2; if (s2 >= NSTAGE) s2 -= NSTAGE;
            ISSUE_P(s2, (t+2)*32);
        }
        MMA_TILE(dynsm + OFF_A(st), dynsm + OFF_B(st));
        if (++st == NSTAGE) st = 0;
    }
    #undef ISSUE_P
    #pragma unroll
    for (int mt = 0; mt < 4; mt++){
        int r1 = r0 + wm + mt*16 + lr;
        #pragma unroll
        for (int nt = 0; nt < 4; nt++){
            int c = wn + nt*8 + lc*2;
            float2 v1, v2;
            v1.x = acc[mt][nt][0]; v1.y = acc[mt][nt][1];
            v2.x = acc[mt][nt][2]; v2.y = acc[mt][nt][3];
            *(float2*)(g_P + (size_t)r1*256 + nb*128 + c) = v1;
            *(float2*)(g_P + (size_t)(r1+8)*256 + nb*128 + c) = v2;
        }
    }
}

// -------- edge MLP layer 1 (factored): m1 = silu(w@Ww + P_i[ii] + P_j[jj] + be1) --------
__global__ void __launch_bounds__(256, 2) edge_mlp1_mma(const float* __restrict__ be1,
                                                        const float* __restrict__ weight,
                                                        const int* __restrict__ ei){
    extern __shared__ uint32_t dynsm[];
    __shared__ float sBias[128];
    __shared__ int s_ii[128], s_jj[128];
    const int tid = threadIdx.x;
    const int e0  = blockIdx.x*128;
    if (tid < 128){
        s_ii[tid] = ei[e0 + tid];
        s_jj[tid] = ei[N_EDGES + e0 + tid];
        sBias[tid] = be1[tid];
    }
    __syncthreads();
    const uint32_t sbase = smem_u32(dynsm);
    const int lane = tid & 31, lr = lane >> 2, lc = lane & 3;
    const int wid = tid >> 5;
    const int wm = (wid & 1)*64, wn = (wid >> 1)*32;
    float acc[4][4][4];
    ACC_ZERO4();
    const int lr8 = tid >> 3, lc8 = tid & 7;

    #define ISSUE1(st, kt) do { \
        uint32_t ab = sbase + OFF_A(st)*4u; \
        uint32_t bb = sbase + OFF_B(st)*4u; \
        _Pragma("unroll") \
        for (int i = 0; i < 4; i++){ \
            int r = lr8 + i*32, c = lc8; \
            int kg = (kt) + c*4; \
            uint32_t off = (uint32_t)(r*32 + (((c ^ r) & 7) << 2))*4u; \
            CP_ASYNC16(ab + off, (const void*)(weight + (size_t)(e0 + r)*EDIM + kg)); \
            CP_ASYNC16(bb + off, (const void*)(g_WwT + (size_t)r*EDIM + kg)); \
        } \
        CP_COMMIT(); \
    } while(0)

    const int T = EDIM/32;   // 13
    ISSUE1(0, 0);
    ISSUE1(1, 32);
    int st = 0;
    for (int t = 0; t < T; t++){
        if (t + 1 < T) CP_WAIT(1); else CP_WAIT(0);
        __syncthreads();
        if (t + 2 < T){
            int s2 = st + 2; if (s2 >= NSTAGE) s2 -= NSTAGE;
            ISSUE1(s2, (t+2)*32);
        }
        MMA_TILE(dynsm + OFF_A(st), dynsm + OFF_B(st));
        if (++st == NSTAGE) st = 0;
    }
    #undef ISSUE1
    #pragma unroll
    for (int mt = 0; mt < 4; mt++){
        int r1 = wm + mt*16 + lr, r2 = r1 + 8;
        const float* P1i = g_P + (size_t)s_ii[r1]*256;
        const float* P1j = g_P + (size_t)s_jj[r1]*256 + 128;
        const float* P2i = g_P + (size_t)s_ii[r2]*256;
        const float* P2j = g_P + (size_t)s_jj[r2]*256 + 128;
        #pragma unroll
        for (int nt = 0; nt < 4; nt++){
            int c = wn + nt*8 + lc*2;
            float2 p1i = *(const float2*)(P1i + c), p1j = *(const float2*)(P1j + c);
            float2 p2i = *(const float2*)(P2i + c), p2j = *(const float2*)(P2j + c);
            float2 v1, v2;
            v1.x = silu_f(acc[mt][nt][0] + p1i.x + p1j.x + sBias[c]);
            v1.y = silu_f(acc[mt][nt][1] + p1i.y + p1j.y + sBias[c+1]);
            v2.x = silu_f(acc[mt][nt][2] + p2i.x + p2j.x + sBias[c]);
            v2.y = silu_f(acc[mt][nt][3] + p2i.y + p2j.y + sBias[c+1]);
            *(float2*)(g_m + (size_t)(e0 + r1)*HID + c) = v1;
            *(float2*)(g_m + (size_t)(e0 + r2)*HID + c) = v2;
        }
    }
}

// -------- edge MLP layer 2 + attention + gated message (no atomics) --------
__global__ void __launch_bounds__(256, 2) edge_mlp2_mma(const float* __restrict__ be2,
                                                        const float* __restrict__ Wa,
                                                        const float* __restrict__ ba){
    extern __shared__ uint32_t dynsm[];
    __shared__ float sBias[128], sWa[128], s_att[128];
    const int tid = threadIdx.x;
    const int e0  = blockIdx.x*128;
    if (tid < 128){
        sBias[tid] = be2[tid];
        sWa[tid] = Wa[tid];
        s_att[tid] = 0.0f;
    }
    __syncthreads();
    const uint32_t sbase = smem_u32(dynsm);
    const int lane = tid & 31, lr = lane >> 2, lc = lane & 3;
    const int wid = tid >> 5;
    const int wm = (wid & 1)*64, wn = (wid >> 1)*32;
    float acc[4][4][4];
    ACC_ZERO4();
    const int lr8 = tid >> 3, lc8 = tid & 7;

    #define ISSUE2(st, kt) do { \
        uint32_t ab = sbase + OFF_A(st)*4u; \
        uint32_t bb = sbase + OFF_B(st)*4u; \
        _Pragma("unroll") \
        for (int i = 0; i < 4; i++){ \
            int r = lr8 + i*32, c = lc8; \
            int kg = (kt) + c*4; \
            uint32_t off = (uint32_t)(r*32 + (((c ^ r) & 7) << 2))*4u; \
            CP_ASYNC16(ab + off, (const void*)(g_m + (size_t)(e0 + r)*HID + kg)); \
            CP_ASYNC16(bb + off, (const void*)(g_We2T + (size_t)r*HID + kg)); \
        } \
        CP_COMMIT(); \
    } while(0)

    ISSUE2(0, 0);
    ISSUE2(1, 32);
    int st = 0;
    for (int t = 0; t < 4; t++){
        if (t + 1 < 4) CP_WAIT(1); else CP_WAIT(0);
        __syncthreads();
        if (t + 2 < 4){
            int s2 = st + 2; if (s2 >= NSTAGE) s2 -= NSTAGE;
            ISSUE2(s2, (t+2)*32);
        }
        MMA_TILE(dynsm + OFF_A(st), dynsm + OFF_B(st));
        if (++st == NSTAGE) st = 0;
    }
    #undef ISSUE2
    #pragma unroll
    for (int mt = 0; mt < 4; mt++){
        float p0 = 0.0f, p1 = 0.0f;
        #pragma unroll
        for (int nt = 0; nt < 4; nt++){
            int c = wn + nt*8 + lc*2;
            float wa0 = sWa[c], wa1 = sWa[c+1];
            float v0 = silu_f(acc[mt][nt][0] + sBias[c]);
            float v1 = silu_f(acc[mt][nt][1] + sBias[c+1]);
            float v2 = silu_f(acc[mt][nt][2] + sBias[c]);
            float v3 = silu_f(acc[mt][nt][3] + sBias[c+1]);
            acc[mt][nt][0]=v0; acc[mt][nt][1]=v1; acc[mt][nt][2]=v2; acc[mt][nt][3]=v3;
            p0 += v0*wa0 + v1*wa1;
            p1 += v2*wa0 + v3*wa1;
        }
        atomicAdd(&s_att[wm + mt*16 + lr], p0);
        atomicAdd(&s_att[wm + mt*16 + lr + 8], p1);
    }
    __syncthreads();
    const float ba0 = ba[0];
    #pragma unroll
    for (int mt = 0; mt < 4; mt++){
        int r1 = wm + mt*16 + lr, r2 = r1 + 8;
        float att1 = silu_f(s_att[r1] + ba0);
        float att2 = silu_f(s_att[r2] + ba0);
        #pragma unroll
        for (int nt = 0; nt < 4; nt++){
            int c = wn + nt*8 + lc*2;
            float2 v1, v2;
            v1.x = acc[mt][nt][0]*att1; v1.y = acc[mt][nt][1]*att1;
            v2.x = acc[mt][nt][2]*att2; v2.y = acc[mt][nt][3]*att2;
            *(float2*)(g_m + (size_t)(e0 + r1)*HID + c) = v1;
            *(float2*)(g_m + (size_t)(e0 + r2)*HID + c) = v2;
        }
    }
}

// -------- edge out: resident A + loop over 4 N-blocks --------
__global__ void __launch_bounds__(256, 2) edge_out_mma(const float* __restrict__ bo,
                                                       const float* __restrict__ weight,
                                                       float* __restrict__ out){
    extern __shared__ uint32_t dynsm[];
    __shared__ float sBias[512];
    const int tid = threadIdx.x;
    const int e0  = blockIdx.x*128;
    sBias[tid] = (tid < EDIM) ? bo[tid] : 0.0f;
    sBias[tid+256] = (tid+256 < EDIM) ? bo[tid+256] : 0.0f;
    __syncthreads();
    const uint32_t sbase = smem_u32(dynsm);
    const int lane = tid & 31, lr = lane >> 2, lc = lane & 3;
    const int wid = tid >> 5;
    const int wm = (wid & 1)*64, wn = (wid >> 1)*32;
    float acc[4][4][4];
    const int lr8 = tid >> 3, lc8 = tid & 7;

    #pragma unroll
    for (int kb = 0; kb < 4; kb++){
        #pragma unroll
        for (int i = 0; i < 4; i++){
            int r = lr8 + i*32, c = lc8;
            uint32_t off = (uint32_t)(kb*4096 + r*32 + (((c ^ r) & 7) << 2))*4u;
            CP_ASYNC16(sbase + off, (const void*)(g_m + (size_t)(e0 + r)*HID + kb*32 + c*4));
        }
    }
    CP_COMMIT();

    #define ISSUE_EO(st, idx) do { \
        int nb_ = (idx) >> 2, tt_ = (idx) & 3; \
        uint32_t bb = sbase + (SM_WORDS + (st)*STG_WORDS)*4u; \
        _Pragma("unroll") \
        for (int i = 0; i < 4; i++){ \
            int r = lr8 + i*32, c = lc8; \
            uint32_t off = (uint32_t)(r*32 + (((c ^ r) & 7) << 2))*4u; \
            CP_ASYNC16(bb + off, (const void*)(g_WoT + (size_t)(nb_*128 + r)*HID + tt_*32 + c*4)); \
        } \
        CP_COMMIT(); \
    } while(0)

    ISSUE_EO(0, 0);
    for (int idx = 0; idx < 16; idx++){
        int nb = idx >> 2, tt = idx & 3, st = idx & 1;
        if (tt == 0) ACC_ZERO4();
        CP_WAIT(0);
        __syncthreads();
        if (idx + 1 < 16) ISSUE_EO((idx+1)&1, idx+1);
        MMA_TILE(dynsm + tt*4096, dynsm + SM_WORDS + st*STG_WORDS);
        if (tt == 3){
            #pragma unroll
            for (int mt = 0; mt < 4; mt++){
                int r1 = e0 + wm + mt*16 + lr;
                #pragma unroll
                for (int nt = 0; nt < 4; nt++){
                    int c = wn + nt*8 + lc*2;
                    int g = nb*128 + c;
                    if (g < EDIM){
                        float2 w1 = *(const float2*)(weight + (size_t)r1*EDIM + g);
                        float2 w2 = *(const float2*)(weight + (size_t)(r1+8)*EDIM + g);
                        float2 v1, v2;
                        v1.x = w1.x + silu_f(acc[mt][nt][0] + sBias[g]);
                        v1.y = w1.y + silu_f(acc[mt][nt][1] + sBias[g+1]);
                        v2.x = w2.x + silu_f(acc[mt][nt][2] + sBias[g]);
                        v2.y = w2.y + silu_f(acc[mt][nt][3] + sBias[g+1]);
                        *(float2*)(out + X_OUT_ELEMS + (size_t)r1*EDIM + g) = v1;
                        *(float2*)(out + X_OUT_ELEMS + (size_t)(r1+8)*EDIM + g) = v2;
                    }
                }
            }
        }
    }
    #undef ISSUE_EO
}

// -------- node MLP 1 (MMA) --------
__global__ void __launch_bounds__(256, 2) node_mlp1_mma(const float* __restrict__ bn1){
    extern __shared__ uint32_t dynsm[];
    __shared__ float sBias[128];
    const int tid = threadIdx.x;
    const int r0  = blockIdx.x*128;
    if (tid < 128) sBias[tid] = bn1[tid];
    __syncthreads();
    const uint32_t sbase = smem_u32(dynsm);
    const int lane = tid & 31, lr = lane >> 2, lc = lane & 3;
    const int wid = tid >> 5;
    const int wm = (wid & 1)*64, wn = (wid >> 1)*32;
    float acc[4][4][4];
    ACC_ZERO4();
    const int lr8 = tid >> 3, lc8 = tid & 7;

    #define ISSUE_N1(st, kt) do { \
        uint32_t ab = sbase + OFF_A(st)*4u; \
        uint32_t bb = sbase + OFF_B(st)*4u; \
        _Pragma("unroll") \
        for (int i = 0; i < 4; i++){ \
            int r = lr8 + i*32, c = lc8; \
            int kg = (kt) + c*4; \
            const void* srcA = (kg < HID) ? (const void*)(g_xh + (size_t)(r0 + r)*HID + kg) \
                                          : (const void*)(g_agg + (size_t)(r0 + r)*HID + (kg - HID)); \
            uint32_t off = (uint32_t)(r*32 + (((c ^ r) & 7) << 2))*4u; \
            CP_ASYNC16(ab + off, srcA); \
            CP_ASYNC16(bb + off, (const void*)(g_WnT1 + (size_t)r*256 + kg)); \
        } \
        CP_COMMIT(); \
    } while(0)

    ISSUE_N1(0, 0);
    ISSUE_N1(1, 32);
    int st = 0;
    for (int t = 0; t < 8; t++){
        if (t + 1 < 8) CP_WAIT(1); else CP_WAIT(0);
        __syncthreads();
        if (t + 2 < 8){
            int s2 = st + 2; if (s2 >= NSTAGE) s2 -= NSTAGE;
            ISSUE_N1(s2, (t+2)*32);
        }
        MMA_TILE(dynsm + OFF_A(st), dynsm + OFF_B(st));
        if (++st == NSTAGE) st = 0;
    }
    #undef ISSUE_N1
    #pragma unroll
    for (int mt = 0; mt < 4; mt++){
        int r1 = r0 + wm + mt*16 + lr;
        #pragma unroll
        for (int nt = 0; nt < 4; nt++){
            int c = wn + nt*8 + lc*2;
            float2 v1, v2;
            v1.x = silu_f(acc[mt][nt][0] + sBias[c]);
            v1.y = silu_f(acc[mt][nt][1] + sBias[c+1]);
            v2.x = silu_f(acc[mt][nt][2] + sBias[c]);
            v2.y = silu_f(acc[mt][nt][3] + sBias[c+1]);
            *(float2*)(g_n1 + (size_t)r1*HID + c) = v1;
            *(float2*)(g_n1 + (size_t)(r1+8)*HID + c) = v2;
        }
    }
}

// -------- node MLP 2 (MMA) + residual --------
__global__ void __launch_bounds__(256, 2) node_mlp2_mma(const float* __restrict__ bn2,
                                                        float* __restrict__ out){
    extern __shared__ uint32_t dynsm[];
    __shared__ float sBias[128];
    const int tid = threadIdx.x;
    const int r0  = blockIdx.x*128;
    if (tid < 128) sBias[tid] = bn2[tid];
    __syncthreads();
    const uint32_t sbase = smem_u32(dynsm);
    const int lane = tid & 31, lr = lane >> 2, lc = lane & 3;
    const int wid = tid >> 5;
    const int wm = (wid & 1)*64, wn = (wid >> 1)*32;
    float acc[4][4][4];
    ACC_ZERO4();
    const int lr8 = tid >> 3, lc8 = tid & 7;

    #define ISSUE_N2(st, kt) do { \
        uint32_t ab = sbase + OFF_A(st)*4u; \
        uint32_t bb = sbase + OFF_B(st)*4u; \
        _Pragma("unroll") \
        for (int i = 0; i < 4; i++){ \
            int r = lr8 + i*32, c = lc8; \
            int kg = (kt) + c*4; \
            uint32_t off = (uint32_t)(r*32 + (((c ^ r) & 7) << 2))*4u; \
            CP_ASYNC16(ab + off, (const void*)(g_n1 + (size_t)(r0 + r)*HID + kg)); \
            CP_ASYNC16(bb + off, (const void*)(g_Wn2T + (size_t)r*HID + kg)); \
        } \
        CP_COMMIT(); \
    } while(0)

    ISSUE_N2(0, 0);
    ISSUE_N2(1, 32);
    int st = 0;
    for (int t = 0; t < 4; t++){
        if (t + 1 < 4) CP_WAIT(1); else CP_WAIT(0);
        __syncthreads();
        if (t + 2 < 4){
            int s2 = st + 2; if (s2 >= NSTAGE) s2 -= NSTAGE;
            ISSUE_N2(s2, (t+2)*32);
        }
        MMA_TILE(dynsm + OFF_A(st), dynsm + OFF_B(st));
        if (++st == NSTAGE) st = 0;
    }
    #undef ISSUE_N2
    #pragma unroll
    for (int mt = 0; mt < 4; mt++){
        int r1 = r0 + wm + mt*16 + lr;
        #pragma unroll
        for (int nt = 0; nt < 4; nt++){
            int c = wn + nt*8 + lc*2;
            if (r1 < N_NODES){
                float2 xh1 = *(const float2*)(g_xh + (size_t)r1*HID + c);
                float2 v1;
                v1.x = xh1.x + silu_f(acc[mt][nt][0] + sBias[c]);
                v1.y = xh1.y + silu_f(acc[mt][nt][1] + sBias[c+1]);
                *(float2*)(out + (size_t)r1*HID + c) = v1;
            }
            if (r1 + 8 < N_NODES){
                float2 xh2 = *(const float2*)(g_xh + (size_t)(r1+8)*HID + c);
                float2 v2;
                v2.x = xh2.x + silu_f(acc[mt][nt][2] + sBias[c]);
                v2.y = xh2.y + silu_f(acc[mt][nt][3] + sBias[c+1]);
                *(float2*)(out + (size_t)(r1+8)*HID + c) = v2;
            }
        }
    }
}

extern "C" void kernel_launch(void* const* d_in, const int* in_sizes, int n_in,
                              void* d_out, int out_size){
    const float* x    = (const float*)d_in[0];
    const float* wgt  = (const float*)d_in[1];
    const float* ln_g = (const float*)d_in[2];
    const float* ln_b = (const float*)d_in[3];
    const float* We1  = (const float*)d_in[4];
    const float* be1  = (const float*)d_in[5];
    const float* We2  = (const float*)d_in[6];
    const float* be2  = (const float*)d_in[7];
    const float* Wa   = (const float*)d_in[8];
    const float* ba   = (const float*)d_in[9];
    const float* Wn1  = (const float*)d_in[10];
    const float* bn1  = (const float*)d_in[11];
    const float* Wn2  = (const float*)d_in[12];
    const float* bn2  = (const float*)d_in[13];
    const float* Wo   = (const float*)d_in[14];
    const float* bo   = (const float*)d_in[15];
    const int*   ei   = (const int*)d_in[16];
    float* out = (float*)d_out;

    cudaFuncSetAttribute(pre_P_mma,     cudaFuncAttributeMaxDynamicSharedMemorySize, SMEM_STD);
    cudaFuncSetAttribute(edge_mlp1_mma, cudaFuncAttributeMaxDynamicSharedMemorySize, SMEM_STD);
    cudaFuncSetAttribute(edge_mlp2_mma, cudaFuncAttributeMaxDynamicSharedMemorySize, SMEM_STD);
    cudaFuncSetAttribute(edge_out_mma,  cudaFuncAttributeMaxDynamicSharedMemorySize, SMEM_EO);
    cudaFuncSetAttribute(node_mlp1_mma, cudaFuncAttributeMaxDynamicSharedMemorySize, SMEM_STD);
    cudaFuncSetAttribute(node_mlp2_mma, cudaFuncAttributeMaxDynamicSharedMemorySize, SMEM_STD);

    setup_kernel<<<(65536 + 255)/256, 256>>>(We1, We2, Wo, Wn1, Wn2);
    ln_kernel<<<(N_NODES + 7)/8, dim3(32, 8)>>>(x, ln_g, ln_b);
    hist_kernel<<<(N_EDGES + 255)/256, 256>>>(ei);
    scan_kernel<<<1, 1024>>>();
    scatter_kernel<<<(N_EDGES + 255)/256, 256>>>(ei);
    pre_P_mma<<<dim3(NODES_PAD/128, 2), 256, SMEM_STD>>>();
    edge_mlp1_mma<<<N_EDGES/128, 256, SMEM_STD>>>(be1, wgt, ei);
    edge_mlp2_mma<<<N_EDGES/128, 256, SMEM_STD>>>(be2, Wa, ba);
    agg_kernel<<<(N_NODES + 31)/32, 1024>>>();
    node_mlp1_mma<<<NODES_PAD/128, 256, SMEM_STD>>>(bn1);
    node_mlp2_mma<<<NODES_PAD/128, 256, SMEM_STD>>>(bn2, out);
    edge_out_mma<<<N_EDGES/128, 256, SMEM_EO>>>(bo, wgt, out);
}